// round 6
// baseline (speedup 1.0000x reference)
#include <cuda_runtime.h>
#include <cstdint>

#define N_PTS 65536
#define KNN   32
#define NKP   15
#define CIN   64
#define COUT  128
#define TM    32
#define NTHR  256
#define INV_SIGMA 10.0f

// ---- shared memory layout (words) ----
#define WSTRIDE     964                       // 964 % 32 == 4 -> conflict-free mma A loads
#define SZ_WEIGHTED (TM * WSTRIDE)            // 30848
#define BSTRIDE     136                       // 136 % 32 == 8 -> conflict-free mma B loads
#define SZ_WS       (CIN * BSTRIDE)           // 8704 per buffer
#define OFF_WS0     (SZ_WEIGHTED)
#define OFF_WS1     (OFF_WS0 + SZ_WS)
#define OFF_KP      (OFF_WS1 + SZ_WS)
#define SMEM_WORDS  (OFF_KP + 48)
#define SMEM_BYTES  (SMEM_WORDS * 4)          // 193216 B

__device__ int g_nb_is64;

// neighbors: int64 (reference dtype) or int32 (JAX default). Values < 65536 =>
// int64 means every odd 32-bit word is zero. Detect once.
__global__ void detect_idx_kernel(const int* __restrict__ nbw) {
    __shared__ int found;
    if (threadIdx.x == 0) found = 0;
    __syncthreads();
    int f = 0;
    for (int i = threadIdx.x; i < 65536; i += blockDim.x)
        if (nbw[2 * i + 1] != 0) f = 1;
    if (f) found = 1;
    __syncthreads();
    if (threadIdx.x == 0) g_nb_is64 = found ? 0 : 1;
}

__device__ __forceinline__ uint32_t tf32_rna(float x) {
    uint32_t y;
    asm("cvt.rna.tf32.f32 %0, %1;" : "=r"(y) : "f"(x));
    return y;
}

__device__ __forceinline__ void mma_tf32(float* d, uint32_t a0, uint32_t a1,
                                         uint32_t a2, uint32_t a3,
                                         uint32_t b0, uint32_t b1) {
    asm volatile(
        "mma.sync.aligned.m16n8k8.row.col.f32.tf32.tf32.f32 "
        "{%0,%1,%2,%3}, {%4,%5,%6,%7}, {%8,%9}, {%0,%1,%2,%3};\n"
        : "+f"(d[0]), "+f"(d[1]), "+f"(d[2]), "+f"(d[3])
        : "r"(a0), "r"(a1), "r"(a2), "r"(a3), "r"(b0), "r"(b1));
}

// async-copy one W[q] slab (64x128 fp32 = 32KB) into a w_s buffer (BSTRIDE pad)
__device__ __forceinline__ void cp_W(const float* __restrict__ Wg, float* w_s,
                                     int q, int tid) {
    const float* src = Wg + q * CIN * COUT;
    #pragma unroll
    for (int i = 0; i < 8; i++) {
        int e4 = i * NTHR + tid;          // float4 index 0..2047
        int c  = e4 >> 5;
        int d4 = e4 & 31;
        uint32_t dst = (uint32_t)__cvta_generic_to_shared(&w_s[c * BSTRIDE + d4 * 4]);
        asm volatile("cp.async.cg.shared.global [%0], [%1], 16;\n"
                     :: "r"(dst), "l"(src + e4 * 4));
    }
    asm volatile("cp.async.commit_group;\n");
}

__global__ __launch_bounds__(NTHR, 1)
void kpconv_kernel(const float* __restrict__ pos,
                   const float* __restrict__ feats,
                   const float* __restrict__ kpts,
                   const float* __restrict__ Wg,
                   const int*   __restrict__ nbw,
                   float*       __restrict__ out)
{
    extern __shared__ float sm[];
    float* weighted = sm;                       // [TM][WSTRIDE], tf32-rounded
    float* ws[2]    = { sm + OFF_WS0, sm + OFF_WS1 };
    float* kp_s     = sm + OFF_KP;

    const int tid  = threadIdx.x;
    const int lane = tid & 31;
    const int warp = tid >> 5;
    const int base = blockIdx.x * TM;
    const int scale = 1 + g_nb_is64;

    // prefetch W[0], W[1] -- fully hidden behind phase 1
    cp_W(Wg, ws[0], 0, tid);
    cp_W(Wg, ws[1], 1, tid);

    if (tid < NKP * 3) kp_s[tid] = kpts[tid];
    __syncthreads();   // kp_s visible

    // ---------------- Phase 1 (fully warp-local, no block syncs) -------------
    // per mi: lane=k computes influences iv[15] in registers; then the same
    // warp consumes them via shfl while lane owns channels (2*lane, 2*lane+1).
    #pragma unroll
    for (int mi = 0; mi < 4; mi++) {
        const int m = warp * 4 + mi;
        const int n = base + m;

        int nbi = nbw[(n * KNN + lane) * scale];
        float px = pos[3 * n],   py = pos[3 * n + 1],   pz = pos[3 * n + 2];
        float rx = pos[3 * nbi]     - px;
        float ry = pos[3 * nbi + 1] - py;
        float rz = pos[3 * nbi + 2] - pz;
        float iv[NKP];
        #pragma unroll
        for (int q = 0; q < NKP; q++) {
            float dx = rx - kp_s[3 * q];
            float dy = ry - kp_s[3 * q + 1];
            float dz = rz - kp_s[3 * q + 2];
            float dist = sqrtf(fmaf(dx, dx, fmaf(dy, dy, dz * dz)));
            iv[q] = fmaxf(0.0f, fmaf(-dist, INV_SIGMA, 1.0f));
        }

        float2 acc[NKP];
        #pragma unroll
        for (int q = 0; q < NKP; q++) acc[q] = make_float2(0.f, 0.f);

        #pragma unroll
        for (int k8 = 0; k8 < 4; k8++) {
            // batch 8 gathers -> high MLP into L2
            float2 f8[8];
            #pragma unroll
            for (int j = 0; j < 8; j++) {
                int nk = __shfl_sync(0xffffffffu, nbi, k8 * 8 + j);
                f8[j] = *(const float2*)&feats[nk * CIN + 2 * lane];
            }
            #pragma unroll
            for (int j = 0; j < 8; j++) {
                int ksrc = k8 * 8 + j;
                #pragma unroll
                for (int q = 0; q < NKP; q++) {
                    float w = __shfl_sync(0xffffffffu, iv[q], ksrc);
                    acc[q].x = fmaf(w, f8[j].x, acc[q].x);
                    acc[q].y = fmaf(w, f8[j].y, acc[q].y);
                }
            }
        }

        #pragma unroll
        for (int q = 0; q < NKP; q++) {
            uint2* dst = (uint2*)&weighted[m * WSTRIDE + q * CIN + 2 * lane];
            *dst = make_uint2(tf32_rna(acc[q].x), tf32_rna(acc[q].y));
        }
    }

    // ------------- Phase 2: out[32][128] = weighted @ W (tf32 mma) -----------
    // warp grid 2(m) x 4(n); warp tile 16x32; double-buffered W via cp.async.
    const int warp_m = warp >> 2;
    const int warp_n = warp & 3;
    const int lane4  = lane & 3;
    const int laneg  = lane >> 2;

    const uint32_t* Abase =
        (const uint32_t*)(weighted + (warp_m * 16 + laneg) * WSTRIDE + lane4);

    float acc2[4][4];
    #pragma unroll
    for (int nt = 0; nt < 4; nt++)
        #pragma unroll
        for (int i = 0; i < 4; i++) acc2[nt][i] = 0.f;

    for (int q = 0; q < NKP; q++) {
        if (q == NKP - 1) { asm volatile("cp.async.wait_group 0;\n"); }
        else              { asm volatile("cp.async.wait_group 1;\n"); }
        __syncthreads();   // buffer q&1 fully populated by all threads
        const float* Bbase = ws[q & 1] + lane4 * BSTRIDE + warp_n * 32 + laneg;

        #pragma unroll
        for (int c8 = 0; c8 < 8; c8++) {
            const uint32_t* A = Abase + q * CIN + c8 * 8;
            uint32_t a0 = A[0];
            uint32_t a1 = A[8 * WSTRIDE];
            uint32_t a2 = A[4];
            uint32_t a3 = A[8 * WSTRIDE + 4];
            const float* B = Bbase + c8 * 8 * BSTRIDE;
            #pragma unroll
            for (int nt = 0; nt < 4; nt++) {
                uint32_t b0 = __float_as_uint(B[nt * 8]);
                uint32_t b1 = __float_as_uint(B[nt * 8 + 4 * BSTRIDE]);
                mma_tf32(acc2[nt], a0, a1, a2, a3, b0, b1);
            }
        }
        __syncthreads();   // all warps done reading buffer q&1
        if (q + 2 < NKP) cp_W(Wg, ws[q & 1], q + 2, tid);
    }

    const int r0 = base + warp_m * 16 + laneg;
    #pragma unroll
    for (int nt = 0; nt < 4; nt++) {
        int col = warp_n * 32 + nt * 8 + lane4 * 2;
        *(float2*)&out[r0 * COUT + col] =
            make_float2(acc2[nt][0], acc2[nt][1]);
        *(float2*)&out[(r0 + 8) * COUT + col] =
            make_float2(acc2[nt][2], acc2[nt][3]);
    }
}

extern "C" void kernel_launch(void* const* d_in, const int* in_sizes, int n_in,
                              void* d_out, int out_size)
{
    const float* pos   = (const float*)d_in[0];
    const float* feats = (const float*)d_in[1];
    const float* kpts  = (const float*)d_in[2];
    const float* Wg    = (const float*)d_in[3];
    const int*   nbw   = (const int*)d_in[4];
    float* out = (float*)d_out;

    cudaFuncSetAttribute(kpconv_kernel,
                         cudaFuncAttributeMaxDynamicSharedMemorySize, SMEM_BYTES);

    detect_idx_kernel<<<1, 256>>>(nbw);
    kpconv_kernel<<<N_PTS / TM, NTHR, SMEM_BYTES>>>(pos, feats, kpts, Wg, nbw, out);
}

// round 7
// speedup vs baseline: 1.1515x; 1.1515x over previous
#include <cuda_runtime.h>
#include <cstdint>

#define N_PTS 65536
#define KNN   32
#define NKP   15
#define CIN   64
#define COUT  128
#define TM    32
#define NTHR  256
#define INV_SIGMA 10.0f

// ---- shared memory layout (words) ----
#define WSTRIDE     964                       // 964 % 32 == 4 -> conflict-free mma A loads
#define SZ_WEIGHTED (TM * WSTRIDE)            // 30848
#define BSTRIDE     136                       // 136 % 32 == 8 -> conflict-free mma B loads
#define SZ_WS       (CIN * BSTRIDE)           // 8704 per buffer
#define OFF_WS0     (SZ_WEIGHTED)             // 30848
#define OFF_WS1     (OFF_WS0 + SZ_WS)         // 39552
#define OFF_INFL    (OFF_WS1 + SZ_WS)         // 48256 ; per-warp 512 words, 8 warps
#define OFF_KP      (OFF_INFL + 8 * KNN * 16) // 52352
#define SMEM_WORDS  (OFF_KP + 48)             // 52400
#define SMEM_BYTES  (SMEM_WORDS * 4)          // 209600 B  (fits 227KB)

__device__ int g_nb_is64;

// neighbors: int64 (reference dtype) or int32 (JAX default). Values < 65536 =>
// int64 means every odd 32-bit word is zero. Detect once.
__global__ void detect_idx_kernel(const int* __restrict__ nbw) {
    __shared__ int found;
    if (threadIdx.x == 0) found = 0;
    __syncthreads();
    int f = 0;
    for (int i = threadIdx.x; i < 65536; i += blockDim.x)
        if (nbw[2 * i + 1] != 0) f = 1;
    if (f) found = 1;
    __syncthreads();
    if (threadIdx.x == 0) g_nb_is64 = found ? 0 : 1;
}

__device__ __forceinline__ uint32_t tf32_rna(float x) {
    uint32_t y;
    asm("cvt.rna.tf32.f32 %0, %1;" : "=r"(y) : "f"(x));
    return y;
}

__device__ __forceinline__ void mma_tf32(float* d, uint32_t a0, uint32_t a1,
                                         uint32_t a2, uint32_t a3,
                                         uint32_t b0, uint32_t b1) {
    asm volatile(
        "mma.sync.aligned.m16n8k8.row.col.f32.tf32.tf32.f32 "
        "{%0,%1,%2,%3}, {%4,%5,%6,%7}, {%8,%9}, {%0,%1,%2,%3};\n"
        : "+f"(d[0]), "+f"(d[1]), "+f"(d[2]), "+f"(d[3])
        : "r"(a0), "r"(a1), "r"(a2), "r"(a3), "r"(b0), "r"(b1));
}

// async-copy one W[q] slab (64x128 fp32 = 32KB) into a w_s buffer (BSTRIDE pad)
__device__ __forceinline__ void cp_W(const float* __restrict__ Wg, float* w_s,
                                     int q, int tid) {
    const float* src = Wg + q * CIN * COUT;
    #pragma unroll
    for (int i = 0; i < 8; i++) {
        int e4 = i * NTHR + tid;          // float4 index 0..2047
        int c  = e4 >> 5;
        int d4 = e4 & 31;
        uint32_t dst = (uint32_t)__cvta_generic_to_shared(&w_s[c * BSTRIDE + d4 * 4]);
        asm volatile("cp.async.cg.shared.global [%0], [%1], 16;\n"
                     :: "r"(dst), "l"(src + e4 * 4));
    }
    asm volatile("cp.async.commit_group;\n");
}

__global__ __launch_bounds__(NTHR, 1)
void kpconv_kernel(const float* __restrict__ pos,
                   const float* __restrict__ feats,
                   const float* __restrict__ kpts,
                   const float* __restrict__ Wg,
                   const int*   __restrict__ nbw,
                   float*       __restrict__ out)
{
    extern __shared__ float sm[];
    float* weighted = sm;                       // [TM][WSTRIDE], tf32-rounded
    float* ws[2]    = { sm + OFF_WS0, sm + OFF_WS1 };
    float* kp_s     = sm + OFF_KP;

    const int tid  = threadIdx.x;
    const int lane = tid & 31;
    const int warp = tid >> 5;
    const int base = blockIdx.x * TM;
    const int scale = 1 + g_nb_is64;

    float* inflw = sm + OFF_INFL + warp * (KNN * 16);  // warp-private [32][16]

    // prefetch W[0], W[1] -- hidden behind phase 1
    cp_W(Wg, ws[0], 0, tid);
    cp_W(Wg, ws[1], 1, tid);

    if (tid < NKP * 3) kp_s[tid] = kpts[tid];
    __syncthreads();   // kp_s visible

    // ---------------- Phase 1 (warp-local; smem broadcast for infl) ----------
    #pragma unroll
    for (int mi = 0; mi < 4; mi++) {
        const int m = warp * 4 + mi;
        const int n = base + m;

        // lane = neighbor k : compute its 15 influences
        int nbi = nbw[(n * KNN + lane) * scale];
        float px = pos[3 * n],   py = pos[3 * n + 1],   pz = pos[3 * n + 2];
        float rx = pos[3 * nbi]     - px;
        float ry = pos[3 * nbi + 1] - py;
        float rz = pos[3 * nbi + 2] - pz;
        float iv[16];
        #pragma unroll
        for (int q = 0; q < NKP; q++) {
            float dx = rx - kp_s[3 * q];
            float dy = ry - kp_s[3 * q + 1];
            float dz = rz - kp_s[3 * q + 2];
            float dist = sqrtf(fmaf(dx, dx, fmaf(dy, dy, dz * dz)));
            iv[q] = fmaxf(0.0f, fmaf(-dist, INV_SIGMA, 1.0f));
        }
        iv[15] = 0.0f;
        {
            float4* dst = (float4*)&inflw[lane * 16];
            dst[0] = make_float4(iv[0],  iv[1],  iv[2],  iv[3]);
            dst[1] = make_float4(iv[4],  iv[5],  iv[6],  iv[7]);
            dst[2] = make_float4(iv[8],  iv[9],  iv[10], iv[11]);
            dst[3] = make_float4(iv[12], iv[13], iv[14], iv[15]);
        }
        __syncwarp();

        // lane = channel pair (2*lane, 2*lane+1) : accumulate over k
        float2 acc[NKP];
        #pragma unroll
        for (int q = 0; q < NKP; q++) acc[q] = make_float2(0.f, 0.f);

        const float4* inflm = (const float4*)inflw;
        #pragma unroll 4
        for (int k = 0; k < KNN; k++) {
            int nk = __shfl_sync(0xffffffffu, nbi, k);
            float2 f = *(const float2*)&feats[nk * CIN + 2 * lane];
            float4 q0 = inflm[k * 4 + 0];   // same addr all lanes -> broadcast
            float4 q1 = inflm[k * 4 + 1];
            float4 q2 = inflm[k * 4 + 2];
            float4 q3 = inflm[k * 4 + 3];
            float wv[16] = {q0.x, q0.y, q0.z, q0.w, q1.x, q1.y, q1.z, q1.w,
                            q2.x, q2.y, q2.z, q2.w, q3.x, q3.y, q3.z, q3.w};
            #pragma unroll
            for (int q = 0; q < NKP; q++) {
                acc[q].x = fmaf(wv[q], f.x, acc[q].x);
                acc[q].y = fmaf(wv[q], f.y, acc[q].y);
            }
        }

        #pragma unroll
        for (int q = 0; q < NKP; q++) {
            uint2* dst = (uint2*)&weighted[m * WSTRIDE + q * CIN + 2 * lane];
            *dst = make_uint2(tf32_rna(acc[q].x), tf32_rna(acc[q].y));
        }
        __syncwarp();   // infl buffer reuse safe
    }

    // ------------- Phase 2: out[32][128] = weighted @ W (tf32 mma) -----------
    // warp grid 2(m) x 4(n); warp tile 16x32; double-buffered W via cp.async.
    const int warp_m = warp >> 2;
    const int warp_n = warp & 3;
    const int lane4  = lane & 3;
    const int laneg  = lane >> 2;

    const uint32_t* Abase =
        (const uint32_t*)(weighted + (warp_m * 16 + laneg) * WSTRIDE + lane4);

    float acc2[4][4];
    #pragma unroll
    for (int nt = 0; nt < 4; nt++)
        #pragma unroll
        for (int i = 0; i < 4; i++) acc2[nt][i] = 0.f;

    for (int q = 0; q < NKP; q++) {
        if (q == NKP - 1) { asm volatile("cp.async.wait_group 0;\n"); }
        else              { asm volatile("cp.async.wait_group 1;\n"); }
        __syncthreads();   // buffer q&1 fully populated; weighted visible block-wide
        const float* Bbase = ws[q & 1] + lane4 * BSTRIDE + warp_n * 32 + laneg;

        #pragma unroll
        for (int c8 = 0; c8 < 8; c8++) {
            const uint32_t* A = Abase + q * CIN + c8 * 8;
            uint32_t a0 = A[0];
            uint32_t a1 = A[8 * WSTRIDE];
            uint32_t a2 = A[4];
            uint32_t a3 = A[8 * WSTRIDE + 4];
            const float* B = Bbase + c8 * 8 * BSTRIDE;
            #pragma unroll
            for (int nt = 0; nt < 4; nt++) {
                uint32_t b0 = __float_as_uint(B[nt * 8]);
                uint32_t b1 = __float_as_uint(B[nt * 8 + 4 * BSTRIDE]);
                mma_tf32(acc2[nt], a0, a1, a2, a3, b0, b1);
            }
        }
        __syncthreads();   // all warps done reading buffer q&1
        if (q + 2 < NKP) cp_W(Wg, ws[q & 1], q + 2, tid);
    }

    const int r0 = base + warp_m * 16 + laneg;
    #pragma unroll
    for (int nt = 0; nt < 4; nt++) {
        int col = warp_n * 32 + nt * 8 + lane4 * 2;
        *(float2*)&out[r0 * COUT + col] =
            make_float2(acc2[nt][0], acc2[nt][1]);
        *(float2*)&out[(r0 + 8) * COUT + col] =
            make_float2(acc2[nt][2], acc2[nt][3]);
    }
}

extern "C" void kernel_launch(void* const* d_in, const int* in_sizes, int n_in,
                              void* d_out, int out_size)
{
    const float* pos   = (const float*)d_in[0];
    const float* feats = (const float*)d_in[1];
    const float* kpts  = (const float*)d_in[2];
    const float* Wg    = (const float*)d_in[3];
    const int*   nbw   = (const int*)d_in[4];
    float* out = (float*)d_out;

    cudaFuncSetAttribute(kpconv_kernel,
                         cudaFuncAttributeMaxDynamicSharedMemorySize, SMEM_BYTES);

    detect_idx_kernel<<<1, 256>>>(nbw);
    kpconv_kernel<<<N_PTS / TM, NTHR, SMEM_BYTES>>>(pos, feats, kpts, Wg, nbw, out);
}

// round 15
// speedup vs baseline: 1.4104x; 1.2249x over previous
#include <cuda_runtime.h>
#include <cstdint>

#define N_PTS 65536
#define KNN   32
#define NKP   15
#define CIN   64
#define COUT  128
#define KDIM  (NKP * CIN)        // 960
#define INV_SIGMA 10.0f

#define SLICE   16384            // points per slice
#define NSLICE  (N_PTS / SLICE)  // 4

// ---------------- global scratch: weighted[SLICE][960] (tf32 bits) ----------
// one slice only (63 MB); reused across slices via in-order stream semantics
__device__ float g_weighted[(size_t)SLICE * KDIM];

__device__ int g_nb_is64;

// neighbors: int64 (reference dtype) or int32 (JAX default). Values < 65536 =>
// int64 means every odd 32-bit word is zero. Detect once.
__global__ void detect_idx_kernel(const int* __restrict__ nbw) {
    __shared__ int found;
    if (threadIdx.x == 0) found = 0;
    __syncthreads();
    int f = 0;
    for (int i = threadIdx.x; i < 65536; i += blockDim.x)
        if (nbw[2 * i + 1] != 0) f = 1;
    if (f) found = 1;
    __syncthreads();
    if (threadIdx.x == 0) g_nb_is64 = found ? 0 : 1;
}

__device__ __forceinline__ uint32_t tf32_rna(float x) {
    uint32_t y;
    asm("cvt.rna.tf32.f32 %0, %1;" : "=r"(y) : "f"(x));
    return y;
}

__device__ __forceinline__ void mma_tf32(float* d, uint32_t a0, uint32_t a1,
                                         uint32_t a2, uint32_t a3,
                                         uint32_t b0, uint32_t b1) {
    asm volatile(
        "mma.sync.aligned.m16n8k8.row.col.f32.tf32.tf32.f32 "
        "{%0,%1,%2,%3}, {%4,%5,%6,%7}, {%8,%9}, {%0,%1,%2,%3};\n"
        : "+f"(d[0]), "+f"(d[1]), "+f"(d[2]), "+f"(d[3])
        : "r"(a0), "r"(a1), "r"(a2), "r"(a3), "r"(b0), "r"(b1));
}

// ============================ Kernel A: gather (one slice) ===================
// 1 point per warp. 8 warps/CTA, small smem -> multiple CTAs per SM.
__global__ __launch_bounds__(256)
void kpconv_gather_kernel(const float* __restrict__ pos,
                          const float* __restrict__ feats,
                          const float* __restrict__ kpts,
                          const int*   __restrict__ nbw,
                          int n0)
{
    __shared__ float infl_s[8][KNN * 16];
    __shared__ float kp_s[48];

    const int tid  = threadIdx.x;
    const int lane = tid & 31;
    const int warp = tid >> 5;
    const int n    = n0 + blockIdx.x * 8 + warp;   // global point id
    const int scale = 1 + g_nb_is64;

    if (tid < NKP * 3) kp_s[tid] = kpts[tid];
    __syncthreads();

    // lane = neighbor k : compute its 15 influences
    int nbi = nbw[(n * KNN + lane) * scale];
    float px = pos[3 * n],   py = pos[3 * n + 1],   pz = pos[3 * n + 2];
    float rx = pos[3 * nbi]     - px;
    float ry = pos[3 * nbi + 1] - py;
    float rz = pos[3 * nbi + 2] - pz;
    float iv[16];
    #pragma unroll
    for (int q = 0; q < NKP; q++) {
        float dx = rx - kp_s[3 * q];
        float dy = ry - kp_s[3 * q + 1];
        float dz = rz - kp_s[3 * q + 2];
        float dist = sqrtf(fmaf(dx, dx, fmaf(dy, dy, dz * dz)));
        iv[q] = fmaxf(0.0f, fmaf(-dist, INV_SIGMA, 1.0f));
    }
    iv[15] = 0.0f;
    {
        float4* dst = (float4*)&infl_s[warp][lane * 16];
        dst[0] = make_float4(iv[0],  iv[1],  iv[2],  iv[3]);
        dst[1] = make_float4(iv[4],  iv[5],  iv[6],  iv[7]);
        dst[2] = make_float4(iv[8],  iv[9],  iv[10], iv[11]);
        dst[3] = make_float4(iv[12], iv[13], iv[14], iv[15]);
    }
    __syncwarp();

    // lane = channel pair (2*lane, 2*lane+1) : accumulate over k
    float2 acc[NKP];
    #pragma unroll
    for (int q = 0; q < NKP; q++) acc[q] = make_float2(0.f, 0.f);

    const float4* inflm = (const float4*)&infl_s[warp][0];
    #pragma unroll 4
    for (int k = 0; k < KNN; k++) {
        int nk = __shfl_sync(0xffffffffu, nbi, k);
        float2 f = *(const float2*)&feats[nk * CIN + 2 * lane];
        float4 q0 = inflm[k * 4 + 0];   // same addr all lanes -> broadcast
        float4 q1 = inflm[k * 4 + 1];
        float4 q2 = inflm[k * 4 + 2];
        float4 q3 = inflm[k * 4 + 3];
        float wv[16] = {q0.x, q0.y, q0.z, q0.w, q1.x, q1.y, q1.z, q1.w,
                        q2.x, q2.y, q2.z, q2.w, q3.x, q3.y, q3.z, q3.w};
        #pragma unroll
        for (int q = 0; q < NKP; q++) {
            acc[q].x = fmaf(wv[q], f.x, acc[q].x);
            acc[q].y = fmaf(wv[q], f.y, acc[q].y);
        }
    }

    float* grow = g_weighted + (size_t)(n - n0) * KDIM;   // slice-local row
    #pragma unroll
    for (int q = 0; q < NKP; q++) {
        uint2 v = make_uint2(tf32_rna(acc[q].x), tf32_rna(acc[q].y));
        *(uint2*)&grow[q * CIN + 2 * lane] = v;
    }
}

// ============================ Kernel B: GEMM (one slice) =====================
// out[n0:n0+SLICE,128] = g_weighted[0:SLICE,960] @ W[960,128] (tf32 mma)
// CTA tile 128x128, 256 threads, warp grid 2(m) x 4(n), warp tile 64x32.
// K chunks of 32, double-buffered cp.async.
#define ASTRIDE 36     // 36 % 32 == 4 -> conflict-free A frag loads
#define BSTR    136    // 136 % 32 == 8 -> conflict-free B frag loads
#define SZ_A    (128 * ASTRIDE)        // 4608 words / buffer
#define SZ_B    (32 * BSTR)            // 4352 words / buffer
#define GB_SMEM_WORDS (2 * SZ_A + 2 * SZ_B)
#define GB_SMEM_BYTES (GB_SMEM_WORDS * 4)   // 71680 B -> 2 CTAs/SM possible
#define NCHUNK  (KDIM / 32)            // 30

__device__ __forceinline__ void cp16(float* dst_s, const float* src_g) {
    uint32_t d = (uint32_t)__cvta_generic_to_shared(dst_s);
    asm volatile("cp.async.cg.shared.global [%0], [%1], 16;\n"
                 :: "r"(d), "l"(src_g));
}

__device__ __forceinline__ void load_chunk(float* a_s, float* w_s,
                                           const float* __restrict__ Wg,
                                           int mrow, int c, int tid) {
    const float* Ag = g_weighted;
    int kc = c * 32;
    // A: 128 rows x 32 cols = 1024 float4 slots
    #pragma unroll
    for (int i = 0; i < 4; i++) {
        int e = i * 256 + tid;      // float4 slot
        int row = e >> 3;
        int seg = e & 7;
        cp16(a_s + row * ASTRIDE + seg * 4,
             Ag + (size_t)(mrow + row) * KDIM + kc + seg * 4);
    }
    // W: 32 rows(k) x 128 cols = 1024 float4 slots
    #pragma unroll
    for (int i = 0; i < 4; i++) {
        int e = i * 256 + tid;
        int row = e >> 5;           // 0..31
        int seg = e & 31;           // seg*4 covers 128 cols
        cp16(w_s + row * BSTR + seg * 4,
             Wg + (size_t)(kc + row) * COUT + seg * 4);
    }
    asm volatile("cp.async.commit_group;\n");
}

__global__ __launch_bounds__(256)
void kpconv_gemm_kernel(const float* __restrict__ Wg,
                        float*       __restrict__ out,
                        int n0)
{
    extern __shared__ float sm[];
    float* a_buf[2] = { sm, sm + SZ_A };
    float* w_buf[2] = { sm + 2 * SZ_A, sm + 2 * SZ_A + SZ_B };

    const int tid  = threadIdx.x;
    const int lane = tid & 31;
    const int warp = tid >> 5;
    const int mrow = blockIdx.x * 128;       // slice-local scratch row
    const int m0   = n0 + mrow;              // global output row

    const int warp_m = warp >> 2;      // 0..1 -> 64 rows
    const int warp_n = warp & 3;       // 0..3 -> 32 cols
    const int lane4  = lane & 3;
    const int laneg  = lane >> 2;

    load_chunk(a_buf[0], w_buf[0], Wg, mrow, 0, tid);
    load_chunk(a_buf[1], w_buf[1], Wg, mrow, 1, tid);

    float acc[4][4][4];                // [mf][nf][reg]
    #pragma unroll
    for (int mf = 0; mf < 4; mf++)
        #pragma unroll
        for (int nf = 0; nf < 4; nf++)
            #pragma unroll
            for (int i = 0; i < 4; i++) acc[mf][nf][i] = 0.f;

    for (int c = 0; c < NCHUNK; c++) {
        if (c == NCHUNK - 1) { asm volatile("cp.async.wait_group 0;\n"); }
        else                 { asm volatile("cp.async.wait_group 1;\n"); }
        __syncthreads();
        const float* As = a_buf[c & 1];
        const float* Ws = w_buf[c & 1];

        #pragma unroll
        for (int k8 = 0; k8 < 4; k8++) {
            uint32_t af[4][4];
            #pragma unroll
            for (int mf = 0; mf < 4; mf++) {
                const float* A = As + (warp_m * 64 + mf * 16 + laneg) * ASTRIDE
                                    + k8 * 8 + lane4;
                af[mf][0] = __float_as_uint(A[0]);
                af[mf][1] = __float_as_uint(A[8 * ASTRIDE]);
                af[mf][2] = __float_as_uint(A[4]);
                af[mf][3] = __float_as_uint(A[8 * ASTRIDE + 4]);
            }
            uint32_t bf[4][2];
            #pragma unroll
            for (int nf = 0; nf < 4; nf++) {
                const float* B = Ws + (k8 * 8 + lane4) * BSTR
                                    + warp_n * 32 + nf * 8 + laneg;
                bf[nf][0] = __float_as_uint(B[0]);
                bf[nf][1] = __float_as_uint(B[4 * BSTR]);
            }
            #pragma unroll
            for (int mf = 0; mf < 4; mf++)
                #pragma unroll
                for (int nf = 0; nf < 4; nf++)
                    mma_tf32(acc[mf][nf], af[mf][0], af[mf][1], af[mf][2],
                             af[mf][3], bf[nf][0], bf[nf][1]);
        }
        __syncthreads();
        if (c + 2 < NCHUNK) load_chunk(a_buf[c & 1], w_buf[c & 1], Wg, mrow, c + 2, tid);
    }

    // epilogue
    #pragma unroll
    for (int mf = 0; mf < 4; mf++) {
        int r = m0 + warp_m * 64 + mf * 16 + laneg;
        #pragma unroll
        for (int nf = 0; nf < 4; nf++) {
            int col = warp_n * 32 + nf * 8 + lane4 * 2;
            *(float2*)&out[(size_t)r * COUT + col] =
                make_float2(acc[mf][nf][0], acc[mf][nf][1]);
            *(float2*)&out[(size_t)(r + 8) * COUT + col] =
                make_float2(acc[mf][nf][2], acc[mf][nf][3]);
        }
    }
}

// ============================ launcher =======================================
// In-order stream: gather(s) fills scratch, gemm(s) drains it before
// gather(s+1) overwrites. All launches fixed-parameter -> graph-capturable.
extern "C" void kernel_launch(void* const* d_in, const int* in_sizes, int n_in,
                              void* d_out, int out_size)
{
    const float* pos   = (const float*)d_in[0];
    const float* feats = (const float*)d_in[1];
    const float* kpts  = (const float*)d_in[2];
    const float* Wg    = (const float*)d_in[3];
    const int*   nbw   = (const int*)d_in[4];
    float* out = (float*)d_out;

    cudaFuncSetAttribute(kpconv_gemm_kernel,
                         cudaFuncAttributeMaxDynamicSharedMemorySize, GB_SMEM_BYTES);

    detect_idx_kernel<<<1, 256>>>(nbw);
    for (int s = 0; s < NSLICE; s++) {
        kpconv_gather_kernel<<<SLICE / 8, 256>>>(pos, feats, kpts, nbw, s * SLICE);
        kpconv_gemm_kernel<<<SLICE / 128, 256, GB_SMEM_BYTES>>>(Wg, out, s * SLICE);
    }
}